// round 1
// baseline (speedup 1.0000x reference)
#include <cuda_runtime.h>
#include <cuda_bf16.h>

#define NN 50000
#define EE 800000
#define ET (EE + NN)          // edges + self loops = 850000
#define HC 128                // H*C
#define HH 4
#define CC 32

// ---------------- device scratch (static, no allocation) ----------------
__device__ float g_xp1[NN * HC];     // layer1 linear out
__device__ float g_h1 [NN * HC];     // layer1 final (relu)
__device__ float g_xp2[NN * HC];     // layer2 linear out
__device__ float g_as [NN * HH];     // alpha_src (per layer, reused)
__device__ float g_ad [NN * HH];     // alpha_dst
__device__ int   g_cnt[NN];          // histogram / scatter cursor
__device__ int   g_rowptr[NN + 1];
__device__ int   g_srcs[ET];         // CSR (by dst) source indices

// ---------------- CSR build ----------------
__global__ void zero_cnt_kernel() {
    int i = blockIdx.x * blockDim.x + threadIdx.x;
    if (i < NN) g_cnt[i] = 0;
}

__global__ void hist_kernel(const int* __restrict__ ei) {
    int e = blockIdx.x * blockDim.x + threadIdx.x;
    if (e >= ET) return;
    int d = (e < EE) ? ei[EE + e] : (e - EE);
    atomicAdd(&g_cnt[d], 1);
}

__global__ void scan_kernel() {
    __shared__ int wsum[32];
    __shared__ int s_carry;
    int tid = threadIdx.x, lane = tid & 31, w = tid >> 5;
    if (tid == 0) { s_carry = 0; g_rowptr[0] = 0; }
    __syncthreads();
    for (int base = 0; base < NN; base += 1024) {
        int i = base + tid;
        int v = (i < NN) ? g_cnt[i] : 0;
        int x = v;
        #pragma unroll
        for (int o = 1; o < 32; o <<= 1) {
            int t = __shfl_up_sync(0xffffffffu, x, o);
            if (lane >= o) x += t;
        }
        if (lane == 31) wsum[w] = x;
        __syncthreads();
        if (w == 0) {
            int y = wsum[lane];
            #pragma unroll
            for (int o = 1; o < 32; o <<= 1) {
                int t = __shfl_up_sync(0xffffffffu, y, o);
                if (lane >= o) y += t;
            }
            wsum[lane] = y;
        }
        __syncthreads();
        int incl  = x + (w > 0 ? wsum[w - 1] : 0);
        int total = wsum[31];
        int carry = s_carry;
        if (i < NN) g_rowptr[i + 1] = carry + incl;
        __syncthreads();
        if (tid == 0) s_carry = carry + total;
        __syncthreads();
    }
}

__global__ void scatter_kernel(const int* __restrict__ ei) {
    int e = blockIdx.x * blockDim.x + threadIdx.x;
    if (e >= ET) return;
    int s, d;
    if (e < EE) { s = ei[e]; d = ei[EE + e]; }
    else        { s = e - EE; d = s; }
    int pos = g_rowptr[d] + atomicAdd(&g_cnt[d], 1);
    g_srcs[pos] = s;
}

// ---------------- GEMM: C[M,128] = A[M,K] * B[K,128] ----------------
// BM=128, BN=128, BK=16, 256 threads, thread tile 8x8
template <int K>
__global__ __launch_bounds__(256) void gemm128_kernel(
    const float* __restrict__ A, const float* __restrict__ B, float* __restrict__ Cmat)
{
    __shared__ float As[16][128];
    __shared__ float Bs[16][128];
    int tid  = threadIdx.x;
    int row0 = blockIdx.x * 128;
    int tx = tid & 15;       // col group: cols tx*8..tx*8+7
    int ty = tid >> 4;       // row group: rows ty*8..ty*8+7

    float acc[8][8];
    #pragma unroll
    for (int i = 0; i < 8; i++)
        #pragma unroll
        for (int j = 0; j < 8; j++) acc[i][j] = 0.f;

    int lr = tid >> 1;           // 0..127 row for A load
    int lk = (tid & 1) * 8;      // 0 or 8
    int bk = tid >> 4;           // 0..15 k-row for B load
    int bn = (tid & 15) * 8;     // col

    for (int k0 = 0; k0 < K; k0 += 16) {
        int grow = row0 + lr;
        if (grow < NN) {
            float4 a0 = *(const float4*)&A[(long)grow * K + k0 + lk];
            float4 a1 = *(const float4*)&A[(long)grow * K + k0 + lk + 4];
            As[lk + 0][lr] = a0.x; As[lk + 1][lr] = a0.y;
            As[lk + 2][lr] = a0.z; As[lk + 3][lr] = a0.w;
            As[lk + 4][lr] = a1.x; As[lk + 5][lr] = a1.y;
            As[lk + 6][lr] = a1.z; As[lk + 7][lr] = a1.w;
        } else {
            #pragma unroll
            for (int j = 0; j < 8; j++) As[lk + j][lr] = 0.f;
        }
        float4 b0 = *(const float4*)&B[(k0 + bk) * 128 + bn];
        float4 b1 = *(const float4*)&B[(k0 + bk) * 128 + bn + 4];
        *(float4*)&Bs[bk][bn]     = b0;
        *(float4*)&Bs[bk][bn + 4] = b1;
        __syncthreads();

        #pragma unroll
        for (int k = 0; k < 16; k++) {
            float ar[8], br[8];
            *(float4*)&ar[0] = *(float4*)&As[k][ty * 8];
            *(float4*)&ar[4] = *(float4*)&As[k][ty * 8 + 4];
            *(float4*)&br[0] = *(float4*)&Bs[k][tx * 8];
            *(float4*)&br[4] = *(float4*)&Bs[k][tx * 8 + 4];
            #pragma unroll
            for (int i = 0; i < 8; i++)
                #pragma unroll
                for (int j = 0; j < 8; j++)
                    acc[i][j] += ar[i] * br[j];
        }
        __syncthreads();
    }

    #pragma unroll
    for (int i = 0; i < 8; i++) {
        int grow = row0 + ty * 8 + i;
        if (grow < NN) {
            *(float4*)&Cmat[(long)grow * 128 + tx * 8]     = *(float4*)&acc[i][0];
            *(float4*)&Cmat[(long)grow * 128 + tx * 8 + 4] = *(float4*)&acc[i][4];
        }
    }
}

// ---------------- attention coefficients: as/ad[n,h] = <xp[n,h,:], att[h,:]> ----------------
__global__ void alpha_kernel(const float* __restrict__ xp,
                             const float* __restrict__ a_src,
                             const float* __restrict__ a_dst,
                             float* __restrict__ as_out, float* __restrict__ ad_out)
{
    int n = blockIdx.x;
    int tid = threadIdx.x;
    int h = tid >> 5, lane = tid & 31;
    float v  = xp[(long)n * HC + tid];
    float s1 = v * a_src[tid];
    float s2 = v * a_dst[tid];
    #pragma unroll
    for (int o = 16; o; o >>= 1) {
        s1 += __shfl_down_sync(0xffffffffu, s1, o);
        s2 += __shfl_down_sync(0xffffffffu, s2, o);
    }
    if (lane == 0) {
        as_out[n * HH + h] = s1;
        ad_out[n * HH + h] = s2;
    }
}

// ---------------- per-destination online-softmax aggregation ----------------
// one block (128 thr) per destination node; warp = head, lane = channel
__global__ void aggregate_kernel(const float* __restrict__ xp,
                                 const float* __restrict__ as_in,
                                 const float* __restrict__ ad_in,
                                 const float* __restrict__ bias,
                                 float* __restrict__ out,
                                 const int* __restrict__ roots,
                                 int do_relu)
{
    int bi   = blockIdx.x;
    int node = roots ? roots[bi] : bi;
    int tid  = threadIdx.x;
    int h = tid >> 5, lane = tid & 31;

    int beg = g_rowptr[node];
    int end = g_rowptr[node + 1];
    float adv = ad_in[node * HH + h];

    float m = -1e30f, l = 0.f, acc = 0.f;
    for (int e = beg; e < end; e++) {
        int s = g_srcs[e];
        float lg = as_in[s * HH + h] + adv;
        lg = lg > 0.f ? lg : 0.2f * lg;                 // leaky_relu(0.2)
        float nm = fmaxf(m, lg);
        float sc = __expf(m - nm);
        float p  = __expf(lg - nm);
        l   = l * sc + p;
        acc = acc * sc + p * xp[(long)s * HC + h * CC + lane];
        m = nm;
    }
    float o = acc / (l + 1e-16f) + bias[h * CC + lane];
    if (do_relu) o = fmaxf(o, 0.f);
    out[(long)bi * HC + tid] = o;
}

// ---------------- launch ----------------
extern "C" void kernel_launch(void* const* d_in, const int* in_sizes, int n_in,
                              void* d_out, int out_size)
{
    const float* x    = (const float*)d_in[0];
    const int*   ei   = (const int*)  d_in[1];
    const int*   root = (const int*)  d_in[2];
    const float* W1   = (const float*)d_in[3];
    const float* as1  = (const float*)d_in[4];
    const float* ad1  = (const float*)d_in[5];
    const float* b1   = (const float*)d_in[6];
    const float* W2   = (const float*)d_in[7];
    const float* as2  = (const float*)d_in[8];
    const float* ad2  = (const float*)d_in[9];
    const float* b2   = (const float*)d_in[10];
    float* out = (float*)d_out;
    int n_roots = in_sizes[2];

    float *d_xp1, *d_h1, *d_xp2, *d_as, *d_ad;
    cudaGetSymbolAddress((void**)&d_xp1, g_xp1);
    cudaGetSymbolAddress((void**)&d_h1,  g_h1);
    cudaGetSymbolAddress((void**)&d_xp2, g_xp2);
    cudaGetSymbolAddress((void**)&d_as,  g_as);
    cudaGetSymbolAddress((void**)&d_ad,  g_ad);

    // ---- build CSR (dst-sorted) ----
    zero_cnt_kernel<<<(NN + 255) / 256, 256>>>();
    hist_kernel<<<(ET + 255) / 256, 256>>>(ei);
    scan_kernel<<<1, 1024>>>();
    zero_cnt_kernel<<<(NN + 255) / 256, 256>>>();
    scatter_kernel<<<(ET + 255) / 256, 256>>>(ei);

    // ---- layer 1 ----
    gemm128_kernel<256><<<(NN + 127) / 128, 256>>>(x, W1, d_xp1);
    alpha_kernel<<<NN, 128>>>(d_xp1, as1, ad1, d_as, d_ad);
    aggregate_kernel<<<NN, 128>>>(d_xp1, d_as, d_ad, b1, d_h1, nullptr, 1);

    // ---- layer 2 (aggregation only at root nodes) ----
    gemm128_kernel<128><<<(NN + 127) / 128, 256>>>(d_h1, W2, d_xp2);
    alpha_kernel<<<NN, 128>>>(d_xp2, as2, ad2, d_as, d_ad);
    aggregate_kernel<<<n_roots, 128>>>(d_xp2, d_as, d_ad, b2, out, root, 0);
}

// round 4
// speedup vs baseline: 1.2193x; 1.2193x over previous
#include <cuda_runtime.h>
#include <cuda_bf16.h>

#define NN 50000
#define EE 800000
#define ET (EE + NN)          // edges + self loops = 850000
#define HC 128                // H*C
#define HH 4
#define CC 32

// ---------------- device scratch (static, no allocation) ----------------
__device__ float g_xp1[NN * HC];     // layer1 linear out (full)
__device__ float g_h1 [NN * HC];     // layer1 final (COMPACTED frontier rows)
__device__ float g_xp2[NN * HC];     // layer2 linear out (COMPACTED)
__device__ float g_as [NN * HH];     // alpha_src (layer1: full idx; layer2: compact idx)
__device__ float g_ad [NN * HH];
__device__ int   g_cnt[NN];          // histogram / scatter cursor
__device__ int   g_rowptr[NN + 1];
__device__ int   g_srcs[ET];         // CSR (by dst) source indices
__device__ int   g_mark[NN];
__device__ int   g_finv[NN];         // node -> compact frontier index
__device__ int   g_flist[NN];        // compact frontier index -> node
__device__ int   g_fcnt;

// ---------------- CSR build ----------------
__global__ void zero_cnt_kernel() {
    int i = blockIdx.x * blockDim.x + threadIdx.x;
    if (i < NN) g_cnt[i] = 0;
}

__global__ void zero_mark_kernel() {
    int i = blockIdx.x * blockDim.x + threadIdx.x;
    if (i < NN) g_mark[i] = 0;
    if (i == 0) g_fcnt = 0;
}

__global__ void hist_kernel(const int* __restrict__ ei) {
    int e = blockIdx.x * blockDim.x + threadIdx.x;
    if (e >= ET) return;
    int d = (e < EE) ? ei[EE + e] : (e - EE);
    atomicAdd(&g_cnt[d], 1);
}

__global__ void scan_kernel() {
    __shared__ int wsum[32];
    __shared__ int s_carry;
    int tid = threadIdx.x, lane = tid & 31, w = tid >> 5;
    if (tid == 0) { s_carry = 0; g_rowptr[0] = 0; }
    __syncthreads();
    for (int base = 0; base < NN; base += 1024) {
        int i = base + tid;
        int v = (i < NN) ? g_cnt[i] : 0;
        int x = v;
        #pragma unroll
        for (int o = 1; o < 32; o <<= 1) {
            int t = __shfl_up_sync(0xffffffffu, x, o);
            if (lane >= o) x += t;
        }
        if (lane == 31) wsum[w] = x;
        __syncthreads();
        if (w == 0) {
            int y = wsum[lane];
            #pragma unroll
            for (int o = 1; o < 32; o <<= 1) {
                int t = __shfl_up_sync(0xffffffffu, y, o);
                if (lane >= o) y += t;
            }
            wsum[lane] = y;
        }
        __syncthreads();
        int incl  = x + (w > 0 ? wsum[w - 1] : 0);
        int total = wsum[31];
        int carry = s_carry;
        if (i < NN) g_rowptr[i + 1] = carry + incl;
        __syncthreads();
        if (tid == 0) s_carry = carry + total;
        __syncthreads();
    }
}

__global__ void scatter_kernel(const int* __restrict__ ei) {
    int e = blockIdx.x * blockDim.x + threadIdx.x;
    if (e >= ET) return;
    int s, d;
    if (e < EE) { s = ei[e]; d = ei[EE + e]; }
    else        { s = e - EE; d = s; }
    int pos = g_rowptr[d] + atomicAdd(&g_cnt[d], 1);
    g_srcs[pos] = s;
}

// ---------------- frontier: roots + sources of in-edges of roots ----------------
__global__ void mark_roots_kernel(const int* __restrict__ roots) {
    int r = roots[blockIdx.x];
    if (threadIdx.x == 0) g_mark[r] = 1;
    int beg = g_rowptr[r], end = g_rowptr[r + 1];
    for (int e = beg + threadIdx.x; e < end; e += 32)
        g_mark[g_srcs[e]] = 1;
}

__global__ void compact_kernel() {
    int i = blockIdx.x * blockDim.x + threadIdx.x;
    int lane = threadIdx.x & 31;
    bool active = (i < NN) && g_mark[i];
    unsigned mask = __ballot_sync(0xffffffffu, active);
    if (!mask) return;
    int leader = __ffs(mask) - 1;
    int base = 0;
    if (lane == leader) base = atomicAdd(&g_fcnt, __popc(mask));
    base = __shfl_sync(0xffffffffu, base, leader);
    if (active) {
        int pos = base + __popc(mask & ((1u << lane) - 1u));
        g_flist[pos] = i;
        g_finv[i] = pos;
    }
}

// ---------------- GEMM: C[M,128] = A[M,K] * B[K,128] (full, M=NN) ----------------
template <int K>
__global__ __launch_bounds__(256) void gemm128_kernel(
    const float* __restrict__ A, const float* __restrict__ B, float* __restrict__ Cmat)
{
    __shared__ float As[16][128];
    __shared__ float Bs[16][128];
    int tid  = threadIdx.x;
    int row0 = blockIdx.x * 128;
    int tx = tid & 15;
    int ty = tid >> 4;

    float acc[8][8];
    #pragma unroll
    for (int i = 0; i < 8; i++)
        #pragma unroll
        for (int j = 0; j < 8; j++) acc[i][j] = 0.f;

    int lr = tid >> 1;
    int lk = (tid & 1) * 8;
    int bk = tid >> 4;
    int bn = (tid & 15) * 8;

    for (int k0 = 0; k0 < K; k0 += 16) {
        int grow = row0 + lr;
        if (grow < NN) {
            float4 a0 = *(const float4*)&A[(long)grow * K + k0 + lk];
            float4 a1 = *(const float4*)&A[(long)grow * K + k0 + lk + 4];
            As[lk + 0][lr] = a0.x; As[lk + 1][lr] = a0.y;
            As[lk + 2][lr] = a0.z; As[lk + 3][lr] = a0.w;
            As[lk + 4][lr] = a1.x; As[lk + 5][lr] = a1.y;
            As[lk + 6][lr] = a1.z; As[lk + 7][lr] = a1.w;
        } else {
            #pragma unroll
            for (int j = 0; j < 8; j++) As[lk + j][lr] = 0.f;
        }
        float4 b0 = *(const float4*)&B[(k0 + bk) * 128 + bn];
        float4 b1 = *(const float4*)&B[(k0 + bk) * 128 + bn + 4];
        *(float4*)&Bs[bk][bn]     = b0;
        *(float4*)&Bs[bk][bn + 4] = b1;
        __syncthreads();

        #pragma unroll
        for (int k = 0; k < 16; k++) {
            float ar[8], br[8];
            *(float4*)&ar[0] = *(float4*)&As[k][ty * 8];
            *(float4*)&ar[4] = *(float4*)&As[k][ty * 8 + 4];
            *(float4*)&br[0] = *(float4*)&Bs[k][tx * 8];
            *(float4*)&br[4] = *(float4*)&Bs[k][tx * 8 + 4];
            #pragma unroll
            for (int i = 0; i < 8; i++)
                #pragma unroll
                for (int j = 0; j < 8; j++)
                    acc[i][j] += ar[i] * br[j];
        }
        __syncthreads();
    }

    #pragma unroll
    for (int i = 0; i < 8; i++) {
        int grow = row0 + ty * 8 + i;
        if (grow < NN) {
            *(float4*)&Cmat[(long)grow * 128 + tx * 8]     = *(float4*)&acc[i][0];
            *(float4*)&Cmat[(long)grow * 128 + tx * 8 + 4] = *(float4*)&acc[i][4];
        }
    }
}

// ---------------- GEMM over compacted frontier rows (M = g_fcnt, K=128) ----------------
__global__ __launch_bounds__(256) void gemm128_front_kernel(
    const float* __restrict__ A, const float* __restrict__ B, float* __restrict__ Cmat)
{
    int M = g_fcnt;
    int row0 = blockIdx.x * 128;
    if (row0 >= M) return;

    __shared__ float As[16][128];
    __shared__ float Bs[16][128];
    int tid  = threadIdx.x;
    int tx = tid & 15;
    int ty = tid >> 4;

    float acc[8][8];
    #pragma unroll
    for (int i = 0; i < 8; i++)
        #pragma unroll
        for (int j = 0; j < 8; j++) acc[i][j] = 0.f;

    int lr = tid >> 1;
    int lk = (tid & 1) * 8;
    int bk = tid >> 4;
    int bn = (tid & 15) * 8;

    for (int k0 = 0; k0 < 128; k0 += 16) {
        int grow = row0 + lr;
        if (grow < M) {
            float4 a0 = *(const float4*)&A[(long)grow * 128 + k0 + lk];
            float4 a1 = *(const float4*)&A[(long)grow * 128 + k0 + lk + 4];
            As[lk + 0][lr] = a0.x; As[lk + 1][lr] = a0.y;
            As[lk + 2][lr] = a0.z; As[lk + 3][lr] = a0.w;
            As[lk + 4][lr] = a1.x; As[lk + 5][lr] = a1.y;
            As[lk + 6][lr] = a1.z; As[lk + 7][lr] = a1.w;
        } else {
            #pragma unroll
            for (int j = 0; j < 8; j++) As[lk + j][lr] = 0.f;
        }
        float4 b0 = *(const float4*)&B[(k0 + bk) * 128 + bn];
        float4 b1 = *(const float4*)&B[(k0 + bk) * 128 + bn + 4];
        *(float4*)&Bs[bk][bn]     = b0;
        *(float4*)&Bs[bk][bn + 4] = b1;
        __syncthreads();

        #pragma unroll
        for (int k = 0; k < 16; k++) {
            float ar[8], br[8];
            *(float4*)&ar[0] = *(float4*)&As[k][ty * 8];
            *(float4*)&ar[4] = *(float4*)&As[k][ty * 8 + 4];
            *(float4*)&br[0] = *(float4*)&Bs[k][tx * 8];
            *(float4*)&br[4] = *(float4*)&Bs[k][tx * 8 + 4];
            #pragma unroll
            for (int i = 0; i < 8; i++)
                #pragma unroll
                for (int j = 0; j < 8; j++)
                    acc[i][j] += ar[i] * br[j];
        }
        __syncthreads();
    }

    #pragma unroll
    for (int i = 0; i < 8; i++) {
        int grow = row0 + ty * 8 + i;
        if (grow < M) {
            *(float4*)&Cmat[(long)grow * 128 + tx * 8]     = *(float4*)&acc[i][0];
            *(float4*)&Cmat[(long)grow * 128 + tx * 8 + 4] = *(float4*)&acc[i][4];
        }
    }
}

// ---------------- attention coefficients ----------------
// limit==nullptr: rows = [0,NN).  limit!=nullptr: rows = [0,*limit) (compacted)
__global__ void alpha_kernel(const float* __restrict__ xp,
                             const float* __restrict__ a_src,
                             const float* __restrict__ a_dst,
                             float* __restrict__ as_out, float* __restrict__ ad_out,
                             const int* __restrict__ limit)
{
    int n = blockIdx.x;
    if (limit && n >= *limit) return;
    int tid = threadIdx.x;
    int h = tid >> 5, lane = tid & 31;
    float v  = xp[(long)n * HC + tid];
    float s1 = v * a_src[tid];
    float s2 = v * a_dst[tid];
    #pragma unroll
    for (int o = 16; o; o >>= 1) {
        s1 += __shfl_down_sync(0xffffffffu, s1, o);
        s2 += __shfl_down_sync(0xffffffffu, s2, o);
    }
    if (lane == 0) {
        as_out[n * HH + h] = s1;
        ad_out[n * HH + h] = s2;
    }
}

// ---------------- layer-1 aggregation at frontier nodes only ----------------
// grid = NN (upper bound); block bi handles frontier index bi; writes COMPACT h1 row bi
__global__ void aggregate1_kernel(const float* __restrict__ xp,
                                  const float* __restrict__ as_in,
                                  const float* __restrict__ ad_in,
                                  const float* __restrict__ bias,
                                  float* __restrict__ out)
{
    int bi = blockIdx.x;
    if (bi >= g_fcnt) return;
    int node = g_flist[bi];
    int tid  = threadIdx.x;
    int h = tid >> 5, lane = tid & 31;

    int beg = g_rowptr[node];
    int end = g_rowptr[node + 1];
    float adv = ad_in[node * HH + h];

    float m = -1e30f, l = 0.f, acc = 0.f;
    for (int e = beg; e < end; e++) {
        int s = g_srcs[e];
        float lg = as_in[s * HH + h] + adv;
        lg = lg > 0.f ? lg : 0.2f * lg;
        float xv = xp[(long)s * HC + h * CC + lane];
        if (lg <= m) {                       // 1 exp per edge (warp-uniform branch)
            float p = __expf(lg - m);
            l += p; acc += p * xv;
        } else {
            float sc = __expf(m - lg);
            l = l * sc + 1.f;
            acc = acc * sc + xv;
            m = lg;
        }
    }
    float o = acc / (l + 1e-16f) + bias[h * CC + lane];
    out[(long)bi * HC + tid] = fmaxf(o, 0.f);   // relu
}

// ---------------- layer-2 aggregation at root nodes (compacted xp2/as/ad) ----------------
__global__ void aggregate2_kernel(const float* __restrict__ xpc,
                                  const float* __restrict__ as_c,
                                  const float* __restrict__ ad_c,
                                  const float* __restrict__ bias,
                                  float* __restrict__ out,
                                  const int* __restrict__ roots)
{
    int bi   = blockIdx.x;
    int node = roots[bi];
    int tid  = threadIdx.x;
    int h = tid >> 5, lane = tid & 31;

    int beg = g_rowptr[node];
    int end = g_rowptr[node + 1];
    float adv = ad_c[g_finv[node] * HH + h];

    float m = -1e30f, l = 0.f, acc = 0.f;
    for (int e = beg; e < end; e++) {
        int fs = g_finv[g_srcs[e]];
        float lg = as_c[fs * HH + h] + adv;
        lg = lg > 0.f ? lg : 0.2f * lg;
        float xv = xpc[(long)fs * HC + h * CC + lane];
        if (lg <= m) {
            float p = __expf(lg - m);
            l += p; acc += p * xv;
        } else {
            float sc = __expf(m - lg);
            l = l * sc + 1.f;
            acc = acc * sc + xv;
            m = lg;
        }
    }
    out[(long)bi * HC + tid] = acc / (l + 1e-16f) + bias[h * CC + lane];
}

// ---------------- launch ----------------
extern "C" void kernel_launch(void* const* d_in, const int* in_sizes, int n_in,
                              void* d_out, int out_size)
{
    const float* x    = (const float*)d_in[0];
    const int*   ei   = (const int*)  d_in[1];
    const int*   root = (const int*)  d_in[2];
    const float* W1   = (const float*)d_in[3];
    const float* as1  = (const float*)d_in[4];
    const float* ad1  = (const float*)d_in[5];
    const float* b1   = (const float*)d_in[6];
    const float* W2   = (const float*)d_in[7];
    const float* as2  = (const float*)d_in[8];
    const float* ad2  = (const float*)d_in[9];
    const float* b2   = (const float*)d_in[10];
    float* out = (float*)d_out;
    int n_roots = in_sizes[2];

    float *d_xp1, *d_h1, *d_xp2, *d_as, *d_ad;
    int *d_fcnt;
    cudaGetSymbolAddress((void**)&d_xp1, g_xp1);
    cudaGetSymbolAddress((void**)&d_h1,  g_h1);
    cudaGetSymbolAddress((void**)&d_xp2, g_xp2);
    cudaGetSymbolAddress((void**)&d_as,  g_as);
    cudaGetSymbolAddress((void**)&d_ad,  g_ad);
    cudaGetSymbolAddress((void**)&d_fcnt, g_fcnt);

    // ---- build CSR (dst-sorted) ----
    zero_cnt_kernel<<<(NN + 255) / 256, 256>>>();
    hist_kernel<<<(ET + 255) / 256, 256>>>(ei);
    scan_kernel<<<1, 1024>>>();
    zero_cnt_kernel<<<(NN + 255) / 256, 256>>>();
    scatter_kernel<<<(ET + 255) / 256, 256>>>(ei);

    // ---- frontier = roots + their in-edge sources ----
    zero_mark_kernel<<<(NN + 255) / 256, 256>>>();
    mark_roots_kernel<<<n_roots, 32>>>(root);
    compact_kernel<<<(NN + 255) / 256, 256>>>();

    // ---- layer 1 (dense linear; aggregation only at frontier) ----
    gemm128_kernel<256><<<(NN + 127) / 128, 256>>>(x, W1, d_xp1);
    alpha_kernel<<<NN, 128>>>(d_xp1, as1, ad1, d_as, d_ad, nullptr);
    aggregate1_kernel<<<NN, 128>>>(d_xp1, d_as, d_ad, b1, d_h1);

    // ---- layer 2 (dense over compacted frontier rows) ----
    gemm128_front_kernel<<<(NN + 127) / 128, 256>>>(d_h1, W2, d_xp2);
    alpha_kernel<<<NN, 128>>>(d_xp2, as2, ad2, d_as, d_ad, d_fcnt);
    aggregate2_kernel<<<n_roots, 128>>>(d_xp2, d_as, d_ad, b2, out, root);
}

// round 5
// speedup vs baseline: 1.5427x; 1.2652x over previous
#include <cuda_runtime.h>
#include <cuda_bf16.h>

#define NN 50000
#define EE 800000
#define ET (EE + NN)          // edges + self loops = 850000
#define HC 128                // H*C
#define HH 4
#define CC 32
#define NB 49                 // scan blocks: ceil(NN/1024)

// ---------------- device scratch (static, no allocation) ----------------
__device__ float g_xp1[NN * HC];     // layer1 linear out (full)
__device__ float g_h1 [NN * HC];     // layer1 final (COMPACTED frontier rows)
__device__ float g_xp2[NN * HC];     // layer2 linear out (COMPACTED)
__device__ float g_as [NN * HH];
__device__ float g_ad [NN * HH];
__device__ int   g_cnt[NN];          // degree histogram / scatter countdown
__device__ int   g_rowptr[NN + 1];
__device__ int   g_srcs[ET];         // CSR (by dst) source indices
__device__ int   g_mark[NN];
__device__ int   g_finv[NN];         // node -> compact frontier index
__device__ int   g_flist[NN];        // compact frontier index -> node
__device__ int   g_fcnt;
__device__ int   g_bsum[NB];
__device__ int   g_boff[NB];

// ---------------- f32x2 helpers ----------------
#define FMA2(acc, a, b) asm("fma.rn.f32x2 %0, %1, %2, %0;" : "+l"(acc) : "l"(a), "l"(b))
#define SPLAT2(dst, s)  asm("mov.b64 %0, {%1, %1};" : "=l"(dst) : "r"(__float_as_uint(s)))
#define UNPACK2(lo, hi, p) asm("mov.b64 {%0, %1}, %2;" : "=r"(lo), "=r"(hi) : "l"(p))

// ---------------- init: zero cnt/mark/fcnt ----------------
__global__ void init_kernel() {
    int i = blockIdx.x * blockDim.x + threadIdx.x;
    if (i < NN) { g_cnt[i] = 0; g_mark[i] = 0; }
    if (i == 0) g_fcnt = 0;
}

__global__ void hist_kernel(const int* __restrict__ ei) {
    int e = blockIdx.x * blockDim.x + threadIdx.x;
    if (e >= ET) return;
    int d = (e < EE) ? ei[EE + e] : (e - EE);
    atomicAdd(&g_cnt[d], 1);
}

// ---------------- 3-phase scan ----------------
__global__ void scan1_kernel() {
    __shared__ int wsum[32];
    int tid = threadIdx.x, lane = tid & 31, w = tid >> 5;
    int i = blockIdx.x * 1024 + tid;
    int v = (i < NN) ? g_cnt[i] : 0;
    int x = v;
    #pragma unroll
    for (int o = 1; o < 32; o <<= 1) {
        int t = __shfl_up_sync(0xffffffffu, x, o);
        if (lane >= o) x += t;
    }
    if (lane == 31) wsum[w] = x;
    __syncthreads();
    if (w == 0) {
        int y = wsum[lane];
        #pragma unroll
        for (int o = 1; o < 32; o <<= 1) {
            int t = __shfl_up_sync(0xffffffffu, y, o);
            if (lane >= o) y += t;
        }
        wsum[lane] = y;
    }
    __syncthreads();
    int incl = x + (w > 0 ? wsum[w - 1] : 0);
    if (i < NN) g_rowptr[i + 1] = incl;
    if (tid == 1023) g_bsum[blockIdx.x] = incl;
}

__global__ void scan2_kernel() {
    int lane = threadIdx.x;
    int carry = 0;
    for (int base = 0; base < NB; base += 32) {
        int idx = base + lane;
        int v = (idx < NB) ? g_bsum[idx] : 0;
        int x = v;
        #pragma unroll
        for (int o = 1; o < 32; o <<= 1) {
            int t = __shfl_up_sync(0xffffffffu, x, o);
            if (lane >= o) x += t;
        }
        if (idx < NB) g_boff[idx] = carry + x - v;
        carry += __shfl_sync(0xffffffffu, x, 31);
    }
    if (lane == 0) g_rowptr[0] = 0;
}

__global__ void scan3_kernel() {
    int i = blockIdx.x * 1024 + threadIdx.x;
    int off = g_boff[blockIdx.x];
    if (i < NN) g_rowptr[i + 1] += off;
}

// scatter with countdown (no second zero pass)
__global__ void scatter_kernel(const int* __restrict__ ei) {
    int e = blockIdx.x * blockDim.x + threadIdx.x;
    if (e >= ET) return;
    int s, d;
    if (e < EE) { s = ei[e]; d = ei[EE + e]; }
    else        { s = e - EE; d = s; }
    int r = atomicSub(&g_cnt[d], 1);
    g_srcs[g_rowptr[d] + r - 1] = s;
}

// ---------------- frontier: roots + sources of in-edges of roots ----------------
__global__ void mark_roots_kernel(const int* __restrict__ roots) {
    int r = roots[blockIdx.x];
    if (threadIdx.x == 0) g_mark[r] = 1;
    int beg = g_rowptr[r], end = g_rowptr[r + 1];
    for (int e = beg + threadIdx.x; e < end; e += 32)
        g_mark[g_srcs[e]] = 1;
}

__global__ void compact_kernel() {
    int i = blockIdx.x * blockDim.x + threadIdx.x;
    int lane = threadIdx.x & 31;
    bool active = (i < NN) && g_mark[i];
    unsigned mask = __ballot_sync(0xffffffffu, active);
    if (!mask) return;
    int leader = __ffs(mask) - 1;
    int base = 0;
    if (lane == leader) base = atomicAdd(&g_fcnt, __popc(mask));
    base = __shfl_sync(0xffffffffu, base, leader);
    if (active) {
        int pos = base + __popc(mask & ((1u << lane) - 1u));
        g_flist[pos] = i;
        g_finv[i] = pos;
    }
}

// ---------------- fused GEMM + alpha: C[M,128] = A[M,K] * B[K,128] ----------------
// f32x2 packed FMAs; epilogue also produces as/ad = <row_h, att_h>.
// FRONT=false: M = NN; FRONT=true: M = g_fcnt.
template <int K, bool FRONT>
__global__ __launch_bounds__(256) void gemm_alpha_kernel(
    const float* __restrict__ A, const float* __restrict__ B, float* __restrict__ Cmat,
    const float* __restrict__ a_src, const float* __restrict__ a_dst,
    float* __restrict__ as_out, float* __restrict__ ad_out)
{
    int M = FRONT ? g_fcnt : NN;
    int row0 = blockIdx.x * 128;
    if (row0 >= M) return;

    __shared__ __align__(16) float As[16][128];
    __shared__ __align__(16) float Bs[16][128];
    int tid = threadIdx.x;
    int tx = tid & 15;       // col group: cols tx*8..tx*8+7
    int ty = tid >> 4;       // row group: rows ty*8..ty*8+7

    unsigned long long acc2[8][4];
    #pragma unroll
    for (int i = 0; i < 8; i++)
        #pragma unroll
        for (int j = 0; j < 4; j++) acc2[i][j] = 0ULL;

    int lr = tid >> 1;           // 0..127 row for A load
    int lk = (tid & 1) * 8;      // 0 or 8
    int bk = tid >> 4;           // 0..15 k-row for B load
    int bn = (tid & 15) * 8;     // col

    for (int k0 = 0; k0 < K; k0 += 16) {
        int grow = row0 + lr;
        if (grow < M) {
            float4 a0 = *(const float4*)&A[(long)grow * K + k0 + lk];
            float4 a1 = *(const float4*)&A[(long)grow * K + k0 + lk + 4];
            As[lk + 0][lr] = a0.x; As[lk + 1][lr] = a0.y;
            As[lk + 2][lr] = a0.z; As[lk + 3][lr] = a0.w;
            As[lk + 4][lr] = a1.x; As[lk + 5][lr] = a1.y;
            As[lk + 6][lr] = a1.z; As[lk + 7][lr] = a1.w;
        } else {
            #pragma unroll
            for (int j = 0; j < 8; j++) As[lk + j][lr] = 0.f;
        }
        float4 b0 = *(const float4*)&B[(k0 + bk) * 128 + bn];
        float4 b1 = *(const float4*)&B[(k0 + bk) * 128 + bn + 4];
        *(float4*)&Bs[bk][bn]     = b0;
        *(float4*)&Bs[bk][bn + 4] = b1;
        __syncthreads();

        #pragma unroll
        for (int k = 0; k < 16; k++) {
            float4 a0 = *(const float4*)&As[k][ty * 8];
            float4 a1 = *(const float4*)&As[k][ty * 8 + 4];
            ulonglong2 bl = *(const ulonglong2*)&Bs[k][tx * 8];
            ulonglong2 bh = *(const ulonglong2*)&Bs[k][tx * 8 + 4];
            unsigned long long br2[4] = {bl.x, bl.y, bh.x, bh.y};
            float ar[8] = {a0.x, a0.y, a0.z, a0.w, a1.x, a1.y, a1.z, a1.w};
            unsigned long long ap[8];
            #pragma unroll
            for (int i = 0; i < 8; i++) SPLAT2(ap[i], ar[i]);
            #pragma unroll
            for (int i = 0; i < 8; i++)
                #pragma unroll
                for (int j = 0; j < 4; j++)
                    FMA2(acc2[i][j], ap[i], br2[j]);
        }
        __syncthreads();
    }

    // attention vectors for this thread's 8-col chunk (within head h = tx>>2)
    float4 av0 = *(const float4*)&a_src[tx * 8];
    float4 av1 = *(const float4*)&a_src[tx * 8 + 4];
    float4 dv0 = *(const float4*)&a_dst[tx * 8];
    float4 dv1 = *(const float4*)&a_dst[tx * 8 + 4];
    int lane = tid & 31;
    int h = tx >> 2;

    #pragma unroll
    for (int i = 0; i < 8; i++) {
        float c[8];
        #pragma unroll
        for (int j = 0; j < 4; j++) {
            unsigned int lo, hi;
            UNPACK2(lo, hi, acc2[i][j]);
            c[2 * j]     = __uint_as_float(lo);
            c[2 * j + 1] = __uint_as_float(hi);
        }
        int grow = row0 + ty * 8 + i;
        bool valid = grow < M;
        if (valid) {
            *(float4*)&Cmat[(long)grow * 128 + tx * 8]     = make_float4(c[0], c[1], c[2], c[3]);
            *(float4*)&Cmat[(long)grow * 128 + tx * 8 + 4] = make_float4(c[4], c[5], c[6], c[7]);
        }
        float s1 = c[0]*av0.x + c[1]*av0.y + c[2]*av0.z + c[3]*av0.w
                 + c[4]*av1.x + c[5]*av1.y + c[6]*av1.z + c[7]*av1.w;
        float s2 = c[0]*dv0.x + c[1]*dv0.y + c[2]*dv0.z + c[3]*dv0.w
                 + c[4]*dv1.x + c[5]*dv1.y + c[6]*dv1.z + c[7]*dv1.w;
        s1 += __shfl_xor_sync(0xffffffffu, s1, 1);
        s1 += __shfl_xor_sync(0xffffffffu, s1, 2);
        s2 += __shfl_xor_sync(0xffffffffu, s2, 1);
        s2 += __shfl_xor_sync(0xffffffffu, s2, 2);
        if (valid && (lane & 3) == 0) {
            as_out[grow * HH + h] = s1;
            ad_out[grow * HH + h] = s2;
        }
    }
}

// ---------------- layer-1 aggregation at frontier nodes only ----------------
__global__ void aggregate1_kernel(const float* __restrict__ xp,
                                  const float* __restrict__ as_in,
                                  const float* __restrict__ ad_in,
                                  const float* __restrict__ bias,
                                  float* __restrict__ out)
{
    int bi = blockIdx.x;
    if (bi >= g_fcnt) return;
    int node = g_flist[bi];
    int tid  = threadIdx.x;
    int h = tid >> 5, lane = tid & 31;

    int beg = g_rowptr[node];
    int end = g_rowptr[node + 1];
    float adv = ad_in[node * HH + h];

    float m = -1e30f, l = 0.f, acc = 0.f;
    for (int e = beg; e < end; e++) {
        int s = g_srcs[e];
        float lg = as_in[s * HH + h] + adv;
        lg = lg > 0.f ? lg : 0.2f * lg;
        float xv = xp[(long)s * HC + h * CC + lane];
        if (lg <= m) {
            float p = __expf(lg - m);
            l += p; acc += p * xv;
        } else {
            float sc = __expf(m - lg);
            l = l * sc + 1.f;
            acc = acc * sc + xv;
            m = lg;
        }
    }
    float o = acc / (l + 1e-16f) + bias[h * CC + lane];
    out[(long)bi * HC + tid] = fmaxf(o, 0.f);   // relu
}

// ---------------- layer-2 aggregation at root nodes (compacted xp2/as/ad) ----------------
__global__ void aggregate2_kernel(const float* __restrict__ xpc,
                                  const float* __restrict__ as_c,
                                  const float* __restrict__ ad_c,
                                  const float* __restrict__ bias,
                                  float* __restrict__ out,
                                  const int* __restrict__ roots)
{
    int bi   = blockIdx.x;
    int node = roots[bi];
    int tid  = threadIdx.x;
    int h = tid >> 5, lane = tid & 31;

    int beg = g_rowptr[node];
    int end = g_rowptr[node + 1];
    float adv = ad_c[g_finv[node] * HH + h];

    float m = -1e30f, l = 0.f, acc = 0.f;
    for (int e = beg; e < end; e++) {
        int fs = g_finv[g_srcs[e]];
        float lg = as_c[fs * HH + h] + adv;
        lg = lg > 0.f ? lg : 0.2f * lg;
        float xv = xpc[(long)fs * HC + h * CC + lane];
        if (lg <= m) {
            float p = __expf(lg - m);
            l += p; acc += p * xv;
        } else {
            float sc = __expf(m - lg);
            l = l * sc + 1.f;
            acc = acc * sc + xv;
            m = lg;
        }
    }
    out[(long)bi * HC + tid] = acc / (l + 1e-16f) + bias[h * CC + lane];
}

// ---------------- launch ----------------
extern "C" void kernel_launch(void* const* d_in, const int* in_sizes, int n_in,
                              void* d_out, int out_size)
{
    const float* x    = (const float*)d_in[0];
    const int*   ei   = (const int*)  d_in[1];
    const int*   root = (const int*)  d_in[2];
    const float* W1   = (const float*)d_in[3];
    const float* as1  = (const float*)d_in[4];
    const float* ad1  = (const float*)d_in[5];
    const float* b1   = (const float*)d_in[6];
    const float* W2   = (const float*)d_in[7];
    const float* as2  = (const float*)d_in[8];
    const float* ad2  = (const float*)d_in[9];
    const float* b2   = (const float*)d_in[10];
    float* out = (float*)d_out;
    int n_roots = in_sizes[2];

    float *d_xp1, *d_h1, *d_xp2, *d_as, *d_ad;
    cudaGetSymbolAddress((void**)&d_xp1, g_xp1);
    cudaGetSymbolAddress((void**)&d_h1,  g_h1);
    cudaGetSymbolAddress((void**)&d_xp2, g_xp2);
    cudaGetSymbolAddress((void**)&d_as,  g_as);
    cudaGetSymbolAddress((void**)&d_ad,  g_ad);

    // ---- build CSR (dst-sorted) ----
    init_kernel<<<NB, 1024>>>();
    hist_kernel<<<(ET + 511) / 512, 512>>>(ei);
    scan1_kernel<<<NB, 1024>>>();
    scan2_kernel<<<1, 32>>>();
    scan3_kernel<<<NB, 1024>>>();
    scatter_kernel<<<(ET + 511) / 512, 512>>>(ei);

    // ---- frontier = roots + their in-edge sources ----
    mark_roots_kernel<<<n_roots, 32>>>(root);
    compact_kernel<<<(NN + 255) / 256, 256>>>();

    // ---- layer 1 (dense linear+alpha fused; aggregation only at frontier) ----
    gemm_alpha_kernel<256, false><<<(NN + 127) / 128, 256>>>(x, W1, d_xp1, as1, ad1, d_as, d_ad);
    aggregate1_kernel<<<NN, 128>>>(d_xp1, d_as, d_ad, b1, d_h1);

    // ---- layer 2 (dense over compacted frontier rows, linear+alpha fused) ----
    gemm_alpha_kernel<128, true><<<(NN + 127) / 128, 256>>>(d_h1, W2, d_xp2, as2, ad2, d_as, d_ad);
    aggregate2_kernel<<<n_roots, 128>>>(d_xp2, d_as, d_ad, b2, out, root);
}

// round 7
// speedup vs baseline: 1.7346x; 1.1244x over previous
#include <cuda_runtime.h>
#include <cuda_bf16.h>

#define NN 50000
#define EE 800000
#define ET (EE + NN)          // edges + self loops = 850000
#define HC 128                // H*C
#define HH 4
#define CC 32
#define NB 49                 // scan blocks: ceil(NN/1024)

// ---------------- device scratch (static, no allocation) ----------------
__device__ float g_xp1[NN * HC];     // layer1 linear out (full)
__device__ float g_h1 [NN * HC];     // layer1 final (COMPACTED frontier rows)
__device__ float g_xp2[NN * HC];     // layer2 linear out (COMPACTED)
__device__ float g_as [NN * HH];
__device__ float g_ad [NN * HH];
__device__ int   g_cnt[NN];          // degree histogram / scatter countdown
__device__ int   g_rowptr[NN + 1];
__device__ int   g_srcs[ET];         // CSR (by dst) source indices
__device__ int   g_mark[NN];
__device__ int   g_finv[NN];         // node -> compact frontier index
__device__ int   g_flist[NN];        // compact frontier index -> node
__device__ int   g_fcnt;
__device__ int   g_bsum[NB];

// ---------------- f32x2 helpers ----------------
#define FMA2(acc, a, b) asm("fma.rn.f32x2 %0, %1, %2, %0;" : "+l"(acc) : "l"(a), "l"(b))
#define SPLAT2(dst, s)  asm("mov.b64 %0, {%1, %1};" : "=l"(dst) : "r"(__float_as_uint(s)))
#define UNPACK2(lo, hi, p) asm("mov.b64 {%0, %1}, %2;" : "=r"(lo), "=r"(hi) : "l"(p))

// ---------------- init: zero cnt/mark/fcnt ----------------
__global__ void init_kernel() {
    int i = blockIdx.x * blockDim.x + threadIdx.x;
    if (i < NN) { g_cnt[i] = 0; g_mark[i] = 0; }
    if (i == 0) g_fcnt = 0;
}

__global__ void hist_kernel(const int* __restrict__ ei) {
    int e = blockIdx.x * blockDim.x + threadIdx.x;
    if (e >= ET) return;
    int d = (e < EE) ? ei[EE + e] : (e - EE);
    atomicAdd(&g_cnt[d], 1);
}

// ---------------- 2-phase scan (block offsets recomputed in phase 2) --------
__global__ void scan1_kernel() {
    __shared__ int wsum[32];
    int tid = threadIdx.x, lane = tid & 31, w = tid >> 5;
    int i = blockIdx.x * 1024 + tid;
    int v = (i < NN) ? g_cnt[i] : 0;
    int x = v;
    #pragma unroll
    for (int o = 1; o < 32; o <<= 1) {
        int t = __shfl_up_sync(0xffffffffu, x, o);
        if (lane >= o) x += t;
    }
    if (lane == 31) wsum[w] = x;
    __syncthreads();
    if (w == 0) {
        int y = wsum[lane];
        #pragma unroll
        for (int o = 1; o < 32; o <<= 1) {
            int t = __shfl_up_sync(0xffffffffu, y, o);
            if (lane >= o) y += t;
        }
        wsum[lane] = y;
    }
    __syncthreads();
    int incl = x + (w > 0 ? wsum[w - 1] : 0);
    if (i < NN) g_rowptr[i + 1] = incl;
    if (tid == 1023) g_bsum[blockIdx.x] = incl;
    if (i == 0) g_rowptr[0] = 0;
}

__global__ void scan3_kernel() {
    __shared__ int s_off;
    int tid = threadIdx.x;
    if (tid < 32) {
        int v = 0;
        if (tid      < (int)blockIdx.x) v += g_bsum[tid];
        if (tid + 32 < (int)blockIdx.x) v += g_bsum[tid + 32];
        #pragma unroll
        for (int o = 16; o; o >>= 1) v += __shfl_xor_sync(0xffffffffu, v, o);
        if (tid == 0) s_off = v;
    }
    __syncthreads();
    int i = blockIdx.x * 1024 + tid;
    if (i < NN && blockIdx.x > 0) g_rowptr[i + 1] += s_off;
}

// scatter with countdown (no second zero pass)
__global__ void scatter_kernel(const int* __restrict__ ei) {
    int e = blockIdx.x * blockDim.x + threadIdx.x;
    if (e >= ET) return;
    int s, d;
    if (e < EE) { s = ei[e]; d = ei[EE + e]; }
    else        { s = e - EE; d = s; }
    int r = atomicSub(&g_cnt[d], 1);
    g_srcs[g_rowptr[d] + r - 1] = s;
}

// ---------------- frontier: roots + sources of in-edges of roots ----------------
__global__ void mark_roots_kernel(const int* __restrict__ roots) {
    int r = roots[blockIdx.x];
    if (threadIdx.x == 0) g_mark[r] = 1;
    int beg = g_rowptr[r], end = g_rowptr[r + 1];
    for (int e = beg + threadIdx.x; e < end; e += 32)
        g_mark[g_srcs[e]] = 1;
}

__global__ void compact_kernel() {
    int i = blockIdx.x * blockDim.x + threadIdx.x;
    int lane = threadIdx.x & 31;
    bool active = (i < NN) && g_mark[i];
    unsigned mask = __ballot_sync(0xffffffffu, active);
    if (!mask) return;
    int leader = __ffs(mask) - 1;
    int base = 0;
    if (lane == leader) base = atomicAdd(&g_fcnt, __popc(mask));
    base = __shfl_sync(0xffffffffu, base, leader);
    if (active) {
        int pos = base + __popc(mask & ((1u << lane) - 1u));
        g_flist[pos] = i;
        g_finv[i] = pos;
    }
}

// ---------------- fused GEMM + alpha, double-buffered smem ----------------
// C[M,128] = A[M,K] * B[K,128]; epilogue produces as/ad = <row_h, att_h>.
template <int K, bool FRONT>
__global__ __launch_bounds__(256) void gemm_alpha_kernel(
    const float* __restrict__ A, const float* __restrict__ B, float* __restrict__ Cmat,
    const float* __restrict__ a_src, const float* __restrict__ a_dst,
    float* __restrict__ as_out, float* __restrict__ ad_out)
{
    constexpr int NC = K / 16;
    int M = FRONT ? g_fcnt : NN;
    int row0 = blockIdx.x * 128;
    if (row0 >= M) return;

    __shared__ __align__(16) float As[2][16][128];
    __shared__ __align__(16) float Bs[2][16][128];
    int tid = threadIdx.x;
    int tx = tid & 15;       // col group: cols tx*8..tx*8+7
    int ty = tid >> 4;       // row group: rows ty*8..ty*8+7

    unsigned long long acc2[8][4];
    #pragma unroll
    for (int i = 0; i < 8; i++)
        #pragma unroll
        for (int j = 0; j < 4; j++) acc2[i][j] = 0ULL;

    int lr = tid >> 1;           // 0..127 row for A load
    int lk = (tid & 1) * 8;      // 0 or 8
    int bk = tid >> 4;           // 0..15 k-row for B load
    int bn = (tid & 15) * 8;     // col

    int grow = row0 + lr;
    bool arow_ok = grow < M;
    const float* Arow = A + (long)grow * K + lk;
    const float* Bp   = B + bk * 128 + bn;

    float4 pa0, pa1, pb0, pb1;
    // prefetch chunk 0
    if (arow_ok) {
        pa0 = *(const float4*)(Arow);
        pa1 = *(const float4*)(Arow + 4);
    } else {
        pa0 = make_float4(0, 0, 0, 0); pa1 = pa0;
    }
    pb0 = *(const float4*)(Bp);
    pb1 = *(const float4*)(Bp + 4);
    {
        As[0][lk + 0][lr] = pa0.x; As[0][lk + 1][lr] = pa0.y;
        As[0][lk + 2][lr] = pa0.z; As[0][lk + 3][lr] = pa0.w;
        As[0][lk + 4][lr] = pa1.x; As[0][lk + 5][lr] = pa1.y;
        As[0][lk + 6][lr] = pa1.z; As[0][lk + 7][lr] = pa1.w;
        *(float4*)&Bs[0][bk][bn]     = pb0;
        *(float4*)&Bs[0][bk][bn + 4] = pb1;
    }
    __syncthreads();

    int buf = 0;
    #pragma unroll
    for (int c = 0; c < NC; c++) {
        if (c + 1 < NC) {
            if (arow_ok) {
                pa0 = *(const float4*)(Arow + (c + 1) * 16);
                pa1 = *(const float4*)(Arow + (c + 1) * 16 + 4);
            }
            pb0 = *(const float4*)(Bp + (c + 1) * 16 * 128);
            pb1 = *(const float4*)(Bp + (c + 1) * 16 * 128 + 4);
        }

        #pragma unroll
        for (int k = 0; k < 16; k++) {
            float4 a0 = *(const float4*)&As[buf][k][ty * 8];
            float4 a1 = *(const float4*)&As[buf][k][ty * 8 + 4];
            ulonglong2 bl = *(const ulonglong2*)&Bs[buf][k][tx * 8];
            ulonglong2 bh = *(const ulonglong2*)&Bs[buf][k][tx * 8 + 4];
            unsigned long long br2[4] = {bl.x, bl.y, bh.x, bh.y};
            float ar[8] = {a0.x, a0.y, a0.z, a0.w, a1.x, a1.y, a1.z, a1.w};
            unsigned long long ap[8];
            #pragma unroll
            for (int i = 0; i < 8; i++) SPLAT2(ap[i], ar[i]);
            #pragma unroll
            for (int i = 0; i < 8; i++)
                #pragma unroll
                for (int j = 0; j < 4; j++)
                    FMA2(acc2[i][j], ap[i], br2[j]);
        }

        if (c + 1 < NC) {
            int nb = buf ^ 1;
            As[nb][lk + 0][lr] = pa0.x; As[nb][lk + 1][lr] = pa0.y;
            As[nb][lk + 2][lr] = pa0.z; As[nb][lk + 3][lr] = pa0.w;
            As[nb][lk + 4][lr] = pa1.x; As[nb][lk + 5][lr] = pa1.y;
            As[nb][lk + 6][lr] = pa1.z; As[nb][lk + 7][lr] = pa1.w;
            *(float4*)&Bs[nb][bk][bn]     = pb0;
            *(float4*)&Bs[nb][bk][bn + 4] = pb1;
            __syncthreads();
            buf = nb;
        }
    }

    // attention vectors for this thread's 8-col chunk (within head h = tx>>2)
    float4 av0 = *(const float4*)&a_src[tx * 8];
    float4 av1 = *(const float4*)&a_src[tx * 8 + 4];
    float4 dv0 = *(const float4*)&a_dst[tx * 8];
    float4 dv1 = *(const float4*)&a_dst[tx * 8 + 4];
    int lane = tid & 31;
    int h = tx >> 2;

    #pragma unroll
    for (int i = 0; i < 8; i++) {
        float c[8];
        #pragma unroll
        for (int j = 0; j < 4; j++) {
            unsigned int lo, hi;
            UNPACK2(lo, hi, acc2[i][j]);
            c[2 * j]     = __uint_as_float(lo);
            c[2 * j + 1] = __uint_as_float(hi);
        }
        int gr = row0 + ty * 8 + i;
        bool valid = gr < M;
        if (valid) {
            *(float4*)&Cmat[(long)gr * 128 + tx * 8]     = make_float4(c[0], c[1], c[2], c[3]);
            *(float4*)&Cmat[(long)gr * 128 + tx * 8 + 4] = make_float4(c[4], c[5], c[6], c[7]);
        }
        float s1 = c[0]*av0.x + c[1]*av0.y + c[2]*av0.z + c[3]*av0.w
                 + c[4]*av1.x + c[5]*av1.y + c[6]*av1.z + c[7]*av1.w;
        float s2 = c[0]*dv0.x + c[1]*dv0.y + c[2]*dv0.z + c[3]*dv0.w
                 + c[4]*dv1.x + c[5]*dv1.y + c[6]*dv1.z + c[7]*dv1.w;
        s1 += __shfl_xor_sync(0xffffffffu, s1, 1);
        s1 += __shfl_xor_sync(0xffffffffu, s1, 2);
        s2 += __shfl_xor_sync(0xffffffffu, s2, 1);
        s2 += __shfl_xor_sync(0xffffffffu, s2, 2);
        if (valid && (lane & 3) == 0) {
            as_out[gr * HH + h] = s1;
            ad_out[gr * HH + h] = s2;
        }
    }
}

// ---------------- two-pass softmax aggregation core ----------------
// warp h of the block handles head h of one destination node.
// pass1: warp-parallel max over edges; pass2: 32 exps at a time, staged in smem,
// then channel-lanes stream acc += p * xp[s].
__device__ __forceinline__ void aggregate_node(
    const float* __restrict__ xp, const float* __restrict__ as_in, float adv,
    int beg, int end, int h, int lane, const int* __restrict__ remap,
    float& accO, float& lO)
{
    __shared__ float sp[HH][32];
    __shared__ int   ss[HH][32];

    // pass 1: max (warp-parallel over edges)
    float m = -1e30f;
    for (int e = beg + lane; e < end; e += 32) {
        int s = g_srcs[e];
        int fs = remap ? remap[s] : s;
        float lg = as_in[fs * HH + h] + adv;
        lg = lg > 0.f ? lg : 0.2f * lg;
        m = fmaxf(m, lg);
    }
    #pragma unroll
    for (int o = 16; o; o >>= 1) m = fmaxf(m, __shfl_xor_sync(0xffffffffu, m, o));

    // pass 2
    float l = 0.f, acc = 0.f;
    for (int base = beg; base < end; base += 32) {
        int e = base + lane;
        int s = 0;
        float p = 0.f;
        if (e < end) {
            s = g_srcs[e];
            if (remap) s = remap[s];
            float lg = as_in[s * HH + h] + adv;
            lg = lg > 0.f ? lg : 0.2f * lg;
            p = __expf(lg - m);
        }
        l += p;
        sp[h][lane] = p;
        ss[h][lane] = s;
        __syncwarp();
        int cnt = min(32, end - base);
        #pragma unroll 4
        for (int i = 0; i < cnt; i++) {
            acc += sp[h][i] * xp[(long)ss[h][i] * HC + h * CC + lane];
        }
        __syncwarp();
    }
    #pragma unroll
    for (int o = 16; o; o >>= 1) l += __shfl_xor_sync(0xffffffffu, l, o);
    accO = acc; lO = l;
}

// ---------------- layer-1 aggregation at frontier nodes only ----------------
__global__ void aggregate1_kernel(const float* __restrict__ xp,
                                  const float* __restrict__ as_in,
                                  const float* __restrict__ ad_in,
                                  const float* __restrict__ bias,
                                  float* __restrict__ out)
{
    int bi = blockIdx.x;
    if (bi >= g_fcnt) return;
    int node = g_flist[bi];
    int tid  = threadIdx.x;
    int h = tid >> 5, lane = tid & 31;

    int beg = g_rowptr[node];
    int end = g_rowptr[node + 1];
    float adv = ad_in[node * HH + h];

    float acc, l;
    aggregate_node(xp, as_in, adv, beg, end, h, lane, nullptr, acc, l);
    float o = acc / (l + 1e-16f) + bias[h * CC + lane];
    out[(long)bi * HC + tid] = fmaxf(o, 0.f);   // relu
}

// ---------------- layer-2 aggregation at root nodes (compacted xp2/as/ad) ----------------
__global__ void aggregate2_kernel(const float* __restrict__ xpc,
                                  const float* __restrict__ as_c,
                                  const float* __restrict__ ad_c,
                                  const float* __restrict__ bias,
                                  float* __restrict__ out,
                                  const int* __restrict__ roots)
{
    int bi   = blockIdx.x;
    int node = roots[bi];
    int tid  = threadIdx.x;
    int h = tid >> 5, lane = tid & 31;

    int beg = g_rowptr[node];
    int end = g_rowptr[node + 1];
    float adv = ad_c[g_finv[node] * HH + h];

    float acc, l;
    aggregate_node(xpc, as_c, adv, beg, end, h, lane, g_finv, acc, l);
    out[(long)bi * HC + tid] = acc / (l + 1e-16f) + bias[h * CC + lane];
}

// ---------------- launch ----------------
extern "C" void kernel_launch(void* const* d_in, const int* in_sizes, int n_in,
                              void* d_out, int out_size)
{
    const float* x    = (const float*)d_in[0];
    const int*   ei   = (const int*)  d_in[1];
    const int*   root = (const int*)  d_in[2];
    const float* W1   = (const float*)d_in[3];
    const float* as1  = (const float*)d_in[4];
    const float* ad1  = (const float*)d_in[5];
    const float* b1   = (const float*)d_in[6];
    const float* W2   = (const float*)d_in[7];
    const float* as2  = (const float*)d_in[8];
    const float* ad2  = (const float*)d_in[9];
    const float* b2   = (const float*)d_in[10];
    float* out = (float*)d_out;
    int n_roots = in_sizes[2];

    float *d_xp1, *d_h1, *d_xp2, *d_as, *d_ad;
    cudaGetSymbolAddress((void**)&d_xp1, g_xp1);
    cudaGetSymbolAddress((void**)&d_h1,  g_h1);
    cudaGetSymbolAddress((void**)&d_xp2, g_xp2);
    cudaGetSymbolAddress((void**)&d_as,  g_as);
    cudaGetSymbolAddress((void**)&d_ad,  g_ad);

    // ---- build CSR (dst-sorted) ----
    init_kernel<<<NB, 1024>>>();
    hist_kernel<<<(ET + 511) / 512, 512>>>(ei);
    scan1_kernel<<<NB, 1024>>>();
    scan3_kernel<<<NB, 1024>>>();
    scatter_kernel<<<(ET + 511) / 512, 512>>>(ei);

    // ---- frontier = roots + their in-edge sources ----
    mark_roots_kernel<<<n_roots, 32>>>(root);
    compact_kernel<<<(NN + 255) / 256, 256>>>();

    // ---- layer 1 (dense linear+alpha fused; aggregation only at frontier) ----
    gemm_alpha_kernel<256, false><<<(NN + 127) / 128, 256>>>(x, W1, d_xp1, as1, ad1, d_as, d_ad);
    aggregate1_kernel<<<NN, 128>>>(d_xp1, d_as, d_ad, b1, d_h1);

    // ---- layer 2 (dense over compacted frontier rows, linear+alpha fused) ----
    gemm_alpha_kernel<128, true><<<(NN + 127) / 128, 256>>>(d_h1, W2, d_xp2, as2, ad2, d_as, d_ad);
    aggregate2_kernel<<<n_roots, 128>>>(d_xp2, d_as, d_ad, b2, out, root);
}